// round 15
// baseline (speedup 1.0000x reference)
#include <cuda_runtime.h>
#include <cstdint>

#define NUM_HEADS 8
#define IN_BITS   64
#define N_STATE   256
#define N_OUT     64
#define K_CONN    8
#define HASH      65536
#define BATCH     128
#define T_STEPS   128
#define TOTAL_IN  320   // IN_BITS + N_STATE

#define WPREC_BLOCKS  BATCH          // IMMA wprec: 1 block per batch, FIRST
#define PACK_BLOCKS   4096           // 16M floats / (256 thr * 16 floats)

// Bit-packed threshold table: bit = (state_mem[n][a] >= 0.5). 2 MB, L2-resident.
__device__ uint32_t g_state_bits[N_STATE * (HASH / 32)];
// Precomputed window contribution mod 2^16: [b][step][neuron]. 8 MB.
__device__ uint16_t g_wacc16[BATCH * T_STEPS * N_STATE];

// D += A * B  (m16n8k32, u8 x u8 -> s32)  -- layout verified in R6 (rel_err 0)
#define MMA_U8(D, a0, a1, a2, a3, b0, b1)                                      \
    asm volatile("mma.sync.aligned.m16n8k32.row.col.s32.u8.u8.s32 "            \
                 "{%0,%1,%2,%3}, {%4,%5,%6,%7}, {%8,%9}, {%0,%1,%2,%3};"       \
                 : "+r"((D)[0]), "+r"((D)[1]), "+r"((D)[2]), "+r"((D)[3])      \
                 : "r"(a0), "r"(a1), "r"(a2), "r"(a3), "r"(b0), "r"(b1));

// ---------------------------------------------------------------------------
// Fused prologue:
//  blocks [0, 128):     wprec via IMMA -- wacc[b*s, n] = W[16384x64]*C[64x256]
//                       as m16n8k32 u8 GEMM. ~2-3 us chip-wide, wave-1.
//  blocks [128, +4096): pack -- bit-pack state_mem 64 MB -> 2 MB, HBM-bound.
// ---------------------------------------------------------------------------
__global__ __launch_bounds__(256)
void fused_pre_kernel(const float* __restrict__ sm,
                      const int*   __restrict__ bits,
                      const int*   __restrict__ state_coeffs)
{
    const int t = threadIdx.x;

    if (blockIdx.x >= WPREC_BLOCKS) {
        // ---- pack path ----
        const int lane = t & 31;
        const int gw   = (blockIdx.x - WPREC_BLOCKS) * 8 + (t >> 5);
        const size_t base = (size_t)gw * 512;         // 512 floats per warp
        float v[16];
        #pragma unroll
        for (int j = 0; j < 16; j++)                  // 16 independent loads
            v[j] = sm[base + (size_t)j * 32 + lane];
        #pragma unroll
        for (int j = 0; j < 16; j++) {
            uint32_t bm = __ballot_sync(0xFFFFFFFFu, v[j] >= 0.5f);
            if (lane == 0) g_state_bits[gw * 16 + j] = bm;
        }
        return;
    }

    // ---- wprec path: block = batch b; warp w = steps [w*16, w*16+16) ----
    __shared__ uint8_t ww [T_STEPS * IN_BITS];   // 8 KB  window bytes [step][k]
    __shared__ uint8_t blo[N_STATE * IN_BITS];   // 16 KB coeff lo bytes [n][k]
    __shared__ uint8_t bhi[N_STATE * IN_BITS];   // 16 KB coeff hi bytes [n][k]

    const int b    = blockIdx.x;
    const int wid  = t >> 5;
    const int lane = t & 31;
    const int g    = lane >> 2;     // groupID
    const int tig  = lane & 3;      // thread-in-group

    // expand window bits -> bytes
    {
        const int4* bits4 = reinterpret_cast<const int4*>(bits + (size_t)b * (T_STEPS * IN_BITS));
        uint32_t* ww32 = reinterpret_cast<uint32_t*>(ww);
        #pragma unroll
        for (int j = 0; j < 8; j++) {
            int4 v = bits4[t + 256 * j];
            ww32[t + 256 * j] = (uint32_t)(v.x & 1) | ((uint32_t)(v.y & 1) << 8)
                              | ((uint32_t)(v.z & 1) << 16) | ((uint32_t)(v.w & 1) << 24);
        }
    }
    // coeff window part -> lo/hi byte planes, row t
    {
        const int4* crow = reinterpret_cast<const int4*>(state_coeffs + (size_t)t * TOTAL_IN);
        uint32_t* lo32 = reinterpret_cast<uint32_t*>(blo) + t * 16;
        uint32_t* hi32 = reinterpret_cast<uint32_t*>(bhi) + t * 16;
        #pragma unroll
        for (int j = 0; j < 16; j++) {
            int4 v = crow[j];
            lo32[j] = (uint32_t)(v.x & 255) | ((uint32_t)(v.y & 255) << 8)
                    | ((uint32_t)(v.z & 255) << 16) | ((uint32_t)(v.w & 255) << 24);
            hi32[j] = (uint32_t)((v.x >> 8) & 255) | ((uint32_t)((v.y >> 8) & 255) << 8)
                    | ((uint32_t)((v.z >> 8) & 255) << 16) | ((uint32_t)((v.w >> 8) & 255) << 24);
        }
    }
    __syncthreads();

    // A fragments for this warp's m16 tile (rows = steps w*16..w*16+15), K=64
    const int r0 = wid * 16 + g, r1 = r0 + 8;
    uint32_t A0[4], A1[4];   // chunk0: k 0..31, chunk1: k 32..63
    A0[0] = *reinterpret_cast<const uint32_t*>(ww + r0 * 64 + tig * 4);
    A0[1] = *reinterpret_cast<const uint32_t*>(ww + r1 * 64 + tig * 4);
    A0[2] = *reinterpret_cast<const uint32_t*>(ww + r0 * 64 + 16 + tig * 4);
    A0[3] = *reinterpret_cast<const uint32_t*>(ww + r1 * 64 + 16 + tig * 4);
    A1[0] = *reinterpret_cast<const uint32_t*>(ww + r0 * 64 + 32 + tig * 4);
    A1[1] = *reinterpret_cast<const uint32_t*>(ww + r1 * 64 + 32 + tig * 4);
    A1[2] = *reinterpret_cast<const uint32_t*>(ww + r0 * 64 + 48 + tig * 4);
    A1[3] = *reinterpret_cast<const uint32_t*>(ww + r1 * 64 + 48 + tig * 4);

    uint32_t* dst32 = reinterpret_cast<uint32_t*>(g_wacc16 + ((size_t)b << 15));

    #pragma unroll 4
    for (int nt = 0; nt < 32; nt++) {
        const int n = nt * 8 + g;                    // this thread's B column
        const uint8_t* bl = blo + n * 64;
        const uint8_t* bh = bhi + n * 64;
        uint32_t Dlo[4] = {0u,0u,0u,0u}, Dhi[4] = {0u,0u,0u,0u};
        {
            uint32_t b0 = *reinterpret_cast<const uint32_t*>(bl + tig * 4);
            uint32_t b1 = *reinterpret_cast<const uint32_t*>(bl + 16 + tig * 4);
            MMA_U8(Dlo, A0[0], A0[1], A0[2], A0[3], b0, b1);
            b0 = *reinterpret_cast<const uint32_t*>(bl + 32 + tig * 4);
            b1 = *reinterpret_cast<const uint32_t*>(bl + 48 + tig * 4);
            MMA_U8(Dlo, A1[0], A1[1], A1[2], A1[3], b0, b1);
        }
        {
            uint32_t b0 = *reinterpret_cast<const uint32_t*>(bh + tig * 4);
            uint32_t b1 = *reinterpret_cast<const uint32_t*>(bh + 16 + tig * 4);
            MMA_U8(Dhi, A0[0], A0[1], A0[2], A0[3], b0, b1);
            b0 = *reinterpret_cast<const uint32_t*>(bh + 32 + tig * 4);
            b1 = *reinterpret_cast<const uint32_t*>(bh + 48 + tig * 4);
            MMA_U8(Dhi, A1[0], A1[1], A1[2], A1[3], b0, b1);
        }
        // D layout: d0=(r0, c), d1=(r0, c+1), d2=(r1, c), d3=(r1, c+1); c = nt*8+2*tig
        const uint32_t c = (uint32_t)(nt * 8 + 2 * tig);
        const uint32_t e0 = (Dlo[0] + (Dhi[0] << 8)) & 0xFFFFu;
        const uint32_t e1 = (Dlo[1] + (Dhi[1] << 8)) & 0xFFFFu;
        const uint32_t e2 = (Dlo[2] + (Dhi[2] << 8)) & 0xFFFFu;
        const uint32_t e3 = (Dlo[3] + (Dhi[3] << 8)) & 0xFFFFu;
        dst32[(r0 << 7) + (c >> 1)] = e0 | (e1 << 16);
        dst32[(r1 << 7) + (c >> 1)] = e2 | (e3 << 16);
    }
}

// ---------------------------------------------------------------------------
// Main scan (byte-identical to R11/R14; ~90 us). One CTA per batch, 256 thr,
// thread t = neuron t. Per-batch wacc slab (64 KB u16) copied to dynamic smem
// once; per step: LDS.U16 + 128 dp2a + 1 L2 gather + byte store + 1 barrier.
// ---------------------------------------------------------------------------
__global__ __launch_bounds__(256, 1)
void ram_scan_kernel(const int*   __restrict__ bits,          // (B, T*64)
                     const int*   __restrict__ state_coeffs,  // (256, 320)
                     const int*   __restrict__ head_conn,     // (8, 64, 8)
                     const int*   __restrict__ head_coeffs,   // (8, 64, 8)
                     const float* __restrict__ head_mem,      // (8, 64, 65536)
                     float*       __restrict__ out)           // (B, 64)
{
    extern __shared__ uint32_t dyn[];
    uint16_t* wacc_s = reinterpret_cast<uint16_t*>(dyn);      // 32768 u16 = 64 KB
    uint32_t* stbuf  = dyn + 16384;                           // [2][64] state words

    const int b = blockIdx.x;
    const int t = threadIdx.x;                                // neuron id

    // ---- copy wacc slab into smem (coalesced, 16 uint4 per thread) ----
    {
        const uint4* src = reinterpret_cast<const uint4*>(g_wacc16 + ((size_t)b << 15));
        uint4* dst = reinterpret_cast<uint4*>(wacc_s);
        #pragma unroll
        for (int i = 0; i < 16; i++) dst[t + 256 * i] = src[t + 256 * i];
    }
    if (t < 128) stbuf[t] = 0u;   // both state buffers zeroed

    // ---- state coefficients as u16 pairs for dp2a ----
    uint32_t c2[128];
    {
        const int4* crow = reinterpret_cast<const int4*>(state_coeffs + (size_t)t * TOTAL_IN);
        #pragma unroll
        for (int k = 0; k < 64; k++) {
            int4 v = crow[16 + k];
            c2[2*k]   = (uint32_t)(v.x & 0xFFFF) | ((uint32_t)v.y << 16);
            c2[2*k+1] = (uint32_t)(v.z & 0xFFFF) | ((uint32_t)v.w << 16);
        }
    }
    __syncthreads();   // wacc_s + stbuf ready

    const uint32_t* prow = g_state_bits + ((size_t)t << 11);   // 2048 words/row

    #pragma unroll 2
    for (int step = 0; step < T_STEPS; step++) {
        const int cur = step & 1, nxt = cur ^ 1;
        const uint4* st4 = reinterpret_cast<const uint4*>(stbuf + cur * 64);

        // window contribution: one LDS.U16 (conflict-free)
        const uint32_t wacc = wacc_s[(step << 8) + t];

        // state dot: 128 dp2a over 16 broadcast uint4, 4 accumulator chains
        uint32_t a0 = 0u, a1 = 0u, a2 = 0u, a3 = 0u;
        #pragma unroll
        for (int q = 0; q < 16; q++) {
            uint4 x = st4[q];
            a0 = __dp2a_lo(c2[8*q+0], x.x, a0); a0 = __dp2a_hi(c2[8*q+1], x.x, a0);
            a1 = __dp2a_lo(c2[8*q+2], x.y, a1); a1 = __dp2a_hi(c2[8*q+3], x.y, a1);
            a2 = __dp2a_lo(c2[8*q+4], x.z, a2); a2 = __dp2a_hi(c2[8*q+5], x.z, a2);
            a3 = __dp2a_lo(c2[8*q+6], x.w, a3); a3 = __dp2a_hi(c2[8*q+7], x.w, a3);
        }
        const uint32_t addr = ((a0 + a1) + (a2 + a3) + wacc) & 0xFFFFu;

        // random gather (L2-resident 2 MB table)
        const uint32_t wword = __ldg(prow + (addr >> 5));

        reinterpret_cast<uint8_t*>(stbuf + nxt * 64)[t] =
            (uint8_t)((wword >> (addr & 31u)) & 1u);
        __syncthreads();   // new state visible; old buffer free
    }

    // ---- Head readout (threads 0..63); T even -> final state in stbuf[0] ----
    if (t < N_OUT) {
        const uint8_t* state_b = reinterpret_cast<const uint8_t*>(stbuf);
        const int* lw = bits + (size_t)b * (T_STEPS * IN_BITS) + (T_STEPS * IN_BITS - 3);
        const int hidx = (lw[0] << 2) + (lw[1] << 1) + lw[2];    // 0..7
        const int o    = t;
        const int base = (hidx * N_OUT + o) * K_CONN;
        uint32_t addr = 0u;
        #pragma unroll
        for (int k = 0; k < K_CONN; k++) {
            int conn = __ldg(head_conn + base + k);
            uint32_t c = (uint32_t)__ldg(head_coeffs + base + k);
            addr += state_b[conn] ? c : 0u;
        }
        addr &= 0xFFFFu;
        out[(size_t)b * N_OUT + o] =
            __ldg(head_mem + (((size_t)(hidx * N_OUT + o)) << 16) + addr);
    }
}

extern "C" void kernel_launch(void* const* d_in, const int* in_sizes, int n_in,
                              void* d_out, int out_size)
{
    const int*   bits         = (const int*)  d_in[0];
    const int*   state_coeffs = (const int*)  d_in[1];
    const float* state_mem    = (const float*)d_in[2];
    const int*   head_conn    = (const int*)  d_in[3];
    const int*   head_coeffs  = (const int*)  d_in[4];
    const float* head_mem     = (const float*)d_in[5];
    float*       out          = (float*)      d_out;

    const int scan_smem = 64 * 1024 + 2 * 64 * 4 + 16;   // wacc slab + stbuf
    cudaFuncSetAttribute(ram_scan_kernel,
                         cudaFuncAttributeMaxDynamicSharedMemorySize, scan_smem);

    fused_pre_kernel<<<WPREC_BLOCKS + PACK_BLOCKS, 256>>>(state_mem, bits, state_coeffs);
    ram_scan_kernel<<<BATCH, 256, scan_smem>>>(bits, state_coeffs,
                                               head_conn, head_coeffs, head_mem, out);
}

// round 16
// speedup vs baseline: 1.0529x; 1.0529x over previous
#include <cuda_runtime.h>
#include <cstdint>

#define NUM_HEADS 8
#define IN_BITS   64
#define N_STATE   256
#define N_OUT     64
#define K_CONN    8
#define HASH      65536
#define BATCH     128
#define T_STEPS   128
#define TOTAL_IN  320   // IN_BITS + N_STATE

// Bit-packed threshold table: bit = (state_mem[n][a] >= 0.5). 2 MB, L2-resident.
__device__ uint32_t g_state_bits[N_STATE * (HASH / 32)];

// D += A * B  (m16n8k32, u8 x u8 -> s32)  -- layout validated R6/R15 (rel_err 0)
#define MMA_U8(D, a0, a1, a2, a3, b0, b1)                                      \
    asm volatile("mma.sync.aligned.m16n8k32.row.col.s32.u8.u8.s32 "            \
                 "{%0,%1,%2,%3}, {%4,%5,%6,%7}, {%8,%9}, {%0,%1,%2,%3};"       \
                 : "+r"((D)[0]), "+r"((D)[1]), "+r"((D)[2]), "+r"((D)[3])      \
                 : "r"(a0), "r"(a1), "r"(a2), "r"(a3), "r"(b0), "r"(b1));

// ---------------------------------------------------------------------------
// Prologue: bit-pack state_mem 64 MB -> 2 MB. EXACT standalone R2/R3 form
// (measured 9.4 us, HBM-roofline). Minimal regs, no smem.
// ---------------------------------------------------------------------------
__global__ void pack_state_mem_kernel(const float* __restrict__ sm)
{
    const int tid  = blockIdx.x * blockDim.x + threadIdx.x;
    const int lane = threadIdx.x & 31;
    const int gw   = tid >> 5;
    const size_t base = (size_t)gw * 128;
    #pragma unroll
    for (int j = 0; j < 4; j++) {
        float v = sm[base + (size_t)j * 32 + lane];
        uint32_t b = __ballot_sync(0xFFFFFFFFu, v >= 0.5f);
        if (lane == 0) g_state_bits[gw * 4 + j] = b;
    }
}

// ---------------------------------------------------------------------------
// Main scan with INLINE IMMA window precompute.
// Phase 1 (per CTA, ~1-2 us): wacc[step][neuron] = W[128x64] x C[64x256]
//   via m16n8k32 u8 MMA (coeff split lo/hi bytes; addr mod 2^16 exact),
//   written directly into the CTA's smem wacc slab.
// Phase 2: the proven scan loop (LDS.U16 + 128 dp2a + 1 L2 gather + 1 bar).
// ---------------------------------------------------------------------------
__global__ __launch_bounds__(256, 1)
void ram_scan_kernel(const int*   __restrict__ bits,          // (B, T*64)
                     const int*   __restrict__ state_coeffs,  // (256, 320)
                     const int*   __restrict__ head_conn,     // (8, 64, 8)
                     const int*   __restrict__ head_coeffs,   // (8, 64, 8)
                     const float* __restrict__ head_mem,      // (8, 64, 65536)
                     float*       __restrict__ out)           // (B, 64)
{
    extern __shared__ uint32_t dyn[];
    uint16_t* wacc_s = reinterpret_cast<uint16_t*>(dyn);          // 64 KB
    uint32_t* stbuf  = dyn + 16384;                               // 512 B
    uint8_t*  ww     = reinterpret_cast<uint8_t*>(dyn + 16512);   // 8 KB window bytes
    uint8_t*  blo    = reinterpret_cast<uint8_t*>(dyn + 18560);   // 16 KB coeff lo
    uint8_t*  bhi    = reinterpret_cast<uint8_t*>(dyn + 22656);   // 16 KB coeff hi

    const int b    = blockIdx.x;
    const int t    = threadIdx.x;
    const int wid  = t >> 5;
    const int lane = t & 31;
    const int g    = lane >> 2;     // groupID
    const int tig  = lane & 3;      // thread-in-group

    // ======================= Phase 1: inline wprec =======================
    // expand window bits -> bytes
    {
        const int4* bits4 = reinterpret_cast<const int4*>(bits + (size_t)b * (T_STEPS * IN_BITS));
        uint32_t* ww32 = reinterpret_cast<uint32_t*>(ww);
        #pragma unroll
        for (int j = 0; j < 8; j++) {
            int4 v = bits4[t + 256 * j];
            ww32[t + 256 * j] = (uint32_t)(v.x & 1) | ((uint32_t)(v.y & 1) << 8)
                              | ((uint32_t)(v.z & 1) << 16) | ((uint32_t)(v.w & 1) << 24);
        }
    }
    // window-part coeffs -> lo/hi byte planes, row t
    {
        const int4* crow = reinterpret_cast<const int4*>(state_coeffs + (size_t)t * TOTAL_IN);
        uint32_t* lo32 = reinterpret_cast<uint32_t*>(blo) + t * 16;
        uint32_t* hi32 = reinterpret_cast<uint32_t*>(bhi) + t * 16;
        #pragma unroll
        for (int j = 0; j < 16; j++) {
            int4 v = crow[j];
            lo32[j] = (uint32_t)(v.x & 255) | ((uint32_t)(v.y & 255) << 8)
                    | ((uint32_t)(v.z & 255) << 16) | ((uint32_t)(v.w & 255) << 24);
            hi32[j] = (uint32_t)((v.x >> 8) & 255) | ((uint32_t)((v.y >> 8) & 255) << 8)
                    | ((uint32_t)((v.z >> 8) & 255) << 16) | ((uint32_t)((v.w >> 8) & 255) << 24);
        }
    }
    __syncthreads();

    {
        // A fragments: warp wid owns step rows [wid*16, wid*16+16), K=64
        const int r0 = wid * 16 + g, r1 = r0 + 8;
        uint32_t A0[4], A1[4];
        A0[0] = *reinterpret_cast<const uint32_t*>(ww + r0 * 64 + tig * 4);
        A0[1] = *reinterpret_cast<const uint32_t*>(ww + r1 * 64 + tig * 4);
        A0[2] = *reinterpret_cast<const uint32_t*>(ww + r0 * 64 + 16 + tig * 4);
        A0[3] = *reinterpret_cast<const uint32_t*>(ww + r1 * 64 + 16 + tig * 4);
        A1[0] = *reinterpret_cast<const uint32_t*>(ww + r0 * 64 + 32 + tig * 4);
        A1[1] = *reinterpret_cast<const uint32_t*>(ww + r1 * 64 + 32 + tig * 4);
        A1[2] = *reinterpret_cast<const uint32_t*>(ww + r0 * 64 + 48 + tig * 4);
        A1[3] = *reinterpret_cast<const uint32_t*>(ww + r1 * 64 + 48 + tig * 4);

        uint32_t* wacc32 = dyn;   // wacc_s viewed as u32 pairs

        #pragma unroll 4
        for (int nt = 0; nt < 32; nt++) {
            const int n = nt * 8 + g;                // B column = neuron
            const uint8_t* bl = blo + n * 64;
            const uint8_t* bh = bhi + n * 64;
            uint32_t Dlo[4] = {0u,0u,0u,0u}, Dhi[4] = {0u,0u,0u,0u};
            {
                uint32_t b0 = *reinterpret_cast<const uint32_t*>(bl + tig * 4);
                uint32_t b1 = *reinterpret_cast<const uint32_t*>(bl + 16 + tig * 4);
                MMA_U8(Dlo, A0[0], A0[1], A0[2], A0[3], b0, b1);
                b0 = *reinterpret_cast<const uint32_t*>(bl + 32 + tig * 4);
                b1 = *reinterpret_cast<const uint32_t*>(bl + 48 + tig * 4);
                MMA_U8(Dlo, A1[0], A1[1], A1[2], A1[3], b0, b1);
            }
            {
                uint32_t b0 = *reinterpret_cast<const uint32_t*>(bh + tig * 4);
                uint32_t b1 = *reinterpret_cast<const uint32_t*>(bh + 16 + tig * 4);
                MMA_U8(Dhi, A0[0], A0[1], A0[2], A0[3], b0, b1);
                b0 = *reinterpret_cast<const uint32_t*>(bh + 32 + tig * 4);
                b1 = *reinterpret_cast<const uint32_t*>(bh + 48 + tig * 4);
                MMA_U8(Dhi, A1[0], A1[1], A1[2], A1[3], b0, b1);
            }
            // D layout: d0=(r0,c) d1=(r0,c+1) d2=(r1,c) d3=(r1,c+1); c = nt*8+2*tig
            const uint32_t c = (uint32_t)(nt * 8 + 2 * tig);
            const uint32_t e0 = (Dlo[0] + (Dhi[0] << 8)) & 0xFFFFu;
            const uint32_t e1 = (Dlo[1] + (Dhi[1] << 8)) & 0xFFFFu;
            const uint32_t e2 = (Dlo[2] + (Dhi[2] << 8)) & 0xFFFFu;
            const uint32_t e3 = (Dlo[3] + (Dhi[3] << 8)) & 0xFFFFu;
            wacc32[(r0 << 7) + (c >> 1)] = e0 | (e1 << 16);
            wacc32[(r1 << 7) + (c >> 1)] = e2 | (e3 << 16);
        }
    }

    // ======================= Phase 2: scan =======================
    if (t < 128) stbuf[t] = 0u;   // both state buffers zeroed

    // state-part coefficients as u16 pairs for dp2a
    uint32_t c2[128];
    {
        const int4* crow = reinterpret_cast<const int4*>(state_coeffs + (size_t)t * TOTAL_IN);
        #pragma unroll
        for (int k = 0; k < 64; k++) {
            int4 v = crow[16 + k];
            c2[2*k]   = (uint32_t)(v.x & 0xFFFF) | ((uint32_t)v.y << 16);
            c2[2*k+1] = (uint32_t)(v.z & 0xFFFF) | ((uint32_t)v.w << 16);
        }
    }
    __syncthreads();   // wacc_s + stbuf ready

    const uint32_t* prow = g_state_bits + ((size_t)t << 11);   // 2048 words/row

    #pragma unroll 2
    for (int step = 0; step < T_STEPS; step++) {
        const int cur = step & 1, nxt = cur ^ 1;
        const uint4* st4 = reinterpret_cast<const uint4*>(stbuf + cur * 64);

        // window contribution: one LDS.U16 (conflict-free)
        const uint32_t wacc = wacc_s[(step << 8) + t];

        // state dot: 128 dp2a over 16 broadcast uint4, 4 accumulator chains
        uint32_t a0 = 0u, a1 = 0u, a2 = 0u, a3 = 0u;
        #pragma unroll
        for (int q = 0; q < 16; q++) {
            uint4 x = st4[q];
            a0 = __dp2a_lo(c2[8*q+0], x.x, a0); a0 = __dp2a_hi(c2[8*q+1], x.x, a0);
            a1 = __dp2a_lo(c2[8*q+2], x.y, a1); a1 = __dp2a_hi(c2[8*q+3], x.y, a1);
            a2 = __dp2a_lo(c2[8*q+4], x.z, a2); a2 = __dp2a_hi(c2[8*q+5], x.z, a2);
            a3 = __dp2a_lo(c2[8*q+6], x.w, a3); a3 = __dp2a_hi(c2[8*q+7], x.w, a3);
        }
        const uint32_t addr = ((a0 + a1) + (a2 + a3) + wacc) & 0xFFFFu;

        // random gather (L2-resident 2 MB table)
        const uint32_t wword = __ldg(prow + (addr >> 5));

        reinterpret_cast<uint8_t*>(stbuf + nxt * 64)[t] =
            (uint8_t)((wword >> (addr & 31u)) & 1u);
        __syncthreads();   // new state visible; old buffer free
    }

    // ---- Head readout (threads 0..63); T even -> final state in stbuf[0] ----
    if (t < N_OUT) {
        const uint8_t* state_b = reinterpret_cast<const uint8_t*>(stbuf);
        const int* lw = bits + (size_t)b * (T_STEPS * IN_BITS) + (T_STEPS * IN_BITS - 3);
        const int hidx = (lw[0] << 2) + (lw[1] << 1) + lw[2];    // 0..7
        const int o    = t;
        const int base = (hidx * N_OUT + o) * K_CONN;
        uint32_t addr = 0u;
        #pragma unroll
        for (int k = 0; k < K_CONN; k++) {
            int conn = __ldg(head_conn + base + k);
            uint32_t c = (uint32_t)__ldg(head_coeffs + base + k);
            addr += state_b[conn] ? c : 0u;
        }
        addr &= 0xFFFFu;
        out[(size_t)b * N_OUT + o] =
            __ldg(head_mem + (((size_t)(hidx * N_OUT + o)) << 16) + addr);
    }
}

extern "C" void kernel_launch(void* const* d_in, const int* in_sizes, int n_in,
                              void* d_out, int out_size)
{
    const int*   bits         = (const int*)  d_in[0];
    const int*   state_coeffs = (const int*)  d_in[1];
    const float* state_mem    = (const float*)d_in[2];
    const int*   head_conn    = (const int*)  d_in[3];
    const int*   head_coeffs  = (const int*)  d_in[4];
    const float* head_mem     = (const float*)d_in[5];
    float*       out          = (float*)      d_out;

    // wacc 64 KB + stbuf 512 B + transient (ww 8K, blo 16K, bhi 16K)
    const int scan_smem = (16384 + 128 + 2048 + 4096 + 4096) * 4;
    cudaFuncSetAttribute(ram_scan_kernel,
                         cudaFuncAttributeMaxDynamicSharedMemorySize, scan_smem);

    pack_state_mem_kernel<<<16384, 256>>>(state_mem);
    ram_scan_kernel<<<BATCH, 256, scan_smem>>>(bits, state_coeffs,
                                               head_conn, head_coeffs, head_mem, out);
}